// round 1
// baseline (speedup 1.0000x reference)
#include <cuda_runtime.h>
#include <cstdint>

// Problem constants (FastPointTransformer)
#define NPTS 131072
#define C    128
#define NH   8
#define DD   16
#define KK   27
#define TP   32          // points per block in GEMM kernels

// ---------------- device scratch (no allocs allowed) ----------------
__device__ __align__(256) float g_nq [NPTS * C];   // normalized q   [N,128]
__device__ __align__(256) float g_v  [NPTS * C];   // v              [N,128]
__device__ __align__(256) float g_acc[NPTS * C];   // attention out  [N,128]
__device__ float g_W3q[C * C];
__device__ float g_W3v[C * C];
__device__ float g_bq2[C];
__device__ float g_bv2[C];
__device__ float g_W2f[3 * C];
__device__ float g_t2[C];
__device__ float g_W1f[9];
__device__ float g_t1[3];
__device__ __align__(16) float g_npe[KK * C];      // normalized pos enc

// ---------------- packed f32x2 FMA (Blackwell; ptxas won't auto-fuse) ----------------
__device__ __forceinline__ float2 ffma2(float2 a, float2 b, float2 c) {
    float2 d;
    asm("{\n\t"
        ".reg .b64 A,B,Cr,Dr;\n\t"
        "mov.b64 A, {%2,%3};\n\t"
        "mov.b64 B, {%4,%5};\n\t"
        "mov.b64 Cr, {%6,%7};\n\t"
        "fma.rn.f32x2 Dr, A, B, Cr;\n\t"
        "mov.b64 {%0,%1}, Dr;\n\t"
        "}"
        : "=f"(d.x), "=f"(d.y)
        : "f"(a.x), "f"(a.y), "f"(b.x), "f"(b.y), "f"(c.x), "f"(c.y));
    return d;
}
__device__ __forceinline__ float2 bc2(float w) { return make_float2(w, w); }

// ---------------- prep: fold BN into affine, normalize pos enc ----------------
__global__ void prep_small(const float* __restrict__ W1, const float* __restrict__ g1,
                           const float* __restrict__ b1, const float* __restrict__ m1,
                           const float* __restrict__ v1,
                           const float* __restrict__ W2, const float* __restrict__ g2,
                           const float* __restrict__ b2, const float* __restrict__ m2,
                           const float* __restrict__ v2,
                           const float* __restrict__ pe) {
    int t = threadIdx.x;  // 256 threads
    if (t < 3) {
        float s = g1[t] * rsqrtf(v1[t] + 1e-5f);
        g_t1[t] = b1[t] - m1[t] * s;
    }
    if (t < 9) {
        int j = t % 3;
        float s = g1[j] * rsqrtf(v1[j] + 1e-5f);
        g_W1f[t] = W1[t] * s;
    }
    if (t < C) {
        float s = g2[t] * rsqrtf(v2[t] + 1e-5f);
        g_t2[t] = b2[t] - m2[t] * s;
        for (int i = 0; i < 3; i++) g_W2f[i * C + t] = W2[i * C + t] * s;
    }
    // normalize inter_pos_enc rows (K*H groups of D)
    for (int g = t; g < KK * NH; g += blockDim.x) {
        float vals[DD];
        float ss = 0.f;
        for (int d = 0; d < DD; d++) { vals[d] = pe[g * DD + d]; ss += vals[d] * vals[d]; }
        float sc = 1.f / fmaxf(sqrtf(ss), 1e-12f);
        for (int d = 0; d < DD; d++) g_npe[g * DD + d] = vals[d] * sc;
    }
}

// Fold W3 into Wq/Wv: W3q = W3@Wq, bq2 = bq + b3@Wq (block 128 handles biases)
__global__ void prep_fold(const float* __restrict__ W3, const float* __restrict__ b3,
                          const float* __restrict__ Wq, const float* __restrict__ bq,
                          const float* __restrict__ Wv, const float* __restrict__ bv) {
    __shared__ float srow[C];
    int k = blockIdx.x, c = threadIdx.x;
    srow[c] = (k < C) ? W3[k * C + c] : b3[c];
    __syncthreads();
    float aq = 0.f, av = 0.f;
#pragma unroll 4
    for (int j = 0; j < C; j++) {
        float s = srow[j];
        aq = fmaf(s, Wq[j * C + c], aq);
        av = fmaf(s, Wv[j * C + c], av);
    }
    if (k < C) { g_W3q[k * C + c] = aq; g_W3v[k * C + c] = av; }
    else       { g_bq2[c] = bq[c] + aq; g_bv2[c] = bv[c] + av; }
}

__global__ void zero_acc() {
    int i = blockIdx.x * blockDim.x + threadIdx.x;
    if (i < NPTS * C / 4) reinterpret_cast<float4*>(g_acc)[i] = make_float4(0.f, 0.f, 0.f, 0.f);
}

// ---------------- fused MLP + Q/V GEMM (K=256) + per-head L2 norm ----------------
__global__ __launch_bounds__(128) void qv_kernel(const float* __restrict__ feats,
                                                 const float* __restrict__ npts,
                                                 const float* __restrict__ Wq,
                                                 const float* __restrict__ Wv) {
    __shared__ __align__(16) float sf[C][TP + 2];   // feats^T, pad->even stride, 8B-aligned pairs
    __shared__ __align__(16) float sh[C][TP + 2];   // h2^T
    __shared__ float sh1[TP][3];

    const int c = threadIdx.x;
    const int n0 = blockIdx.x * TP;

#pragma unroll
    for (int p = 0; p < TP; p++) sf[c][p] = feats[(size_t)(n0 + p) * C + c];

    if (c < TP) {
        float p0 = npts[(size_t)(n0 + c) * 3 + 0];
        float p1 = npts[(size_t)(n0 + c) * 3 + 1];
        float p2 = npts[(size_t)(n0 + c) * 3 + 2];
#pragma unroll
        for (int j = 0; j < 3; j++) {
            float h = p0 * g_W1f[j] + p1 * g_W1f[3 + j] + p2 * g_W1f[6 + j] + g_t1[j];
            sh1[c][j] = fmaxf(h, 0.f);
        }
    }
    __syncthreads();

    {
        float w0 = g_W2f[c], w1 = g_W2f[C + c], w2 = g_W2f[2 * C + c], tt = g_t2[c];
#pragma unroll
        for (int p = 0; p < TP; p++)
            sh[c][p] = fmaxf(sh1[p][0] * w0 + sh1[p][1] * w1 + sh1[p][2] * w2 + tt, 0.f);
    }
    __syncthreads();

    float bq0 = g_bq2[c], bv0 = g_bv2[c];
    float2 aq[TP / 2], av[TP / 2];
#pragma unroll
    for (int i = 0; i < TP / 2; i++) { aq[i] = make_float2(bq0, bq0); av[i] = make_float2(bv0, bv0); }

#pragma unroll 2
    for (int k = 0; k < C; k++) {
        float2 wq  = bc2(Wq[k * C + c]);
        float2 wv  = bc2(Wv[k * C + c]);
        float2 w3q = bc2(g_W3q[k * C + c]);
        float2 w3v = bc2(g_W3v[k * C + c]);
#pragma unroll
        for (int i = 0; i < TP / 2; i++) {
            float2 f = *reinterpret_cast<const float2*>(&sf[k][2 * i]);
            float2 h = *reinterpret_cast<const float2*>(&sh[k][2 * i]);
            aq[i] = ffma2(f, wq, aq[i]);
            aq[i] = ffma2(h, w3q, aq[i]);
            av[i] = ffma2(f, wv, av[i]);
            av[i] = ffma2(h, w3v, av[i]);
        }
    }

    // per-head (16-lane) L2 norm of q; write nq and v
#pragma unroll
    for (int i = 0; i < TP / 2; i++) {
        float sx = aq[i].x * aq[i].x;
        float sy = aq[i].y * aq[i].y;
#pragma unroll
        for (int off = 8; off > 0; off >>= 1) {
            sx += __shfl_xor_sync(0xffffffffu, sx, off);
            sy += __shfl_xor_sync(0xffffffffu, sy, off);
        }
        float scx = 1.f / fmaxf(sqrtf(sx), 1e-12f);
        float scy = 1.f / fmaxf(sqrtf(sy), 1e-12f);
        size_t n = (size_t)(n0 + 2 * i);
        g_nq[n * C + c]       = aq[i].x * scx;
        g_nq[(n + 1) * C + c] = aq[i].y * scy;
        g_v [n * C + c]       = av[i].x;
        g_v [(n + 1) * C + c] = av[i].y;
    }
}

// ---------------- fused attn-dot + scatter (warp per pair, v4 reductions) ----------------
__global__ __launch_bounds__(256) void attn_scatter(const int* __restrict__ qidx,
                                                    const int* __restrict__ kidx,
                                                    const int* __restrict__ kern,
                                                    int M) {
    __shared__ __align__(16) float s_npe[KK * C];
    for (int i = threadIdx.x; i < KK * C; i += 256) s_npe[i] = g_npe[i];
    __syncthreads();

    const int lane   = threadIdx.x & 31;
    const int warp   = (blockIdx.x * 256 + threadIdx.x) >> 5;
    const int nwarps = (gridDim.x * 256) >> 5;

    for (int m = warp; m < M; m += nwarps) {
        int q   = qidx[m];
        int key = kidx[m];
        int kk  = kern[m];

        float4 a = reinterpret_cast<const float4*>(g_nq + (size_t)q * C)[lane];
        float4 b = *reinterpret_cast<const float4*>(s_npe + kk * C + lane * 4);
        float part = a.x * b.x + a.y * b.y + a.z * b.z + a.w * b.w;
        // reduce over D=16 -> 4 lanes per head-quad
        part += __shfl_xor_sync(0xffffffffu, part, 1);
        part += __shfl_xor_sync(0xffffffffu, part, 2);

        float4 vv = reinterpret_cast<const float4*>(g_v + (size_t)key * C)[lane];
        float* dst = g_acc + (size_t)q * C + lane * 4;
        asm volatile("red.global.add.v4.f32 [%0], {%1,%2,%3,%4};"
                     :: "l"(dst), "f"(part * vv.x), "f"(part * vv.y),
                        "f"(part * vv.z), "f"(part * vv.w)
                     : "memory");
    }
}

// ---------------- epilogue GEMM: out = acc @ Wo + bo ----------------
__global__ __launch_bounds__(128) void out_kernel(const float* __restrict__ Wo,
                                                  const float* __restrict__ bo,
                                                  float* __restrict__ out) {
    __shared__ __align__(16) float sa[C][TP + 2];
    const int c = threadIdx.x;
    const int n0 = blockIdx.x * TP;

#pragma unroll
    for (int p = 0; p < TP; p++) sa[c][p] = g_acc[(size_t)(n0 + p) * C + c];
    __syncthreads();

    float b = bo[c];
    float2 acc[TP / 2];
#pragma unroll
    for (int i = 0; i < TP / 2; i++) acc[i] = make_float2(b, b);

#pragma unroll 2
    for (int k = 0; k < C; k++) {
        float2 w = bc2(Wo[k * C + c]);
#pragma unroll
        for (int i = 0; i < TP / 2; i++) {
            float2 f = *reinterpret_cast<const float2*>(&sa[k][2 * i]);
            acc[i] = ffma2(f, w, acc[i]);
        }
    }
#pragma unroll
    for (int i = 0; i < TP / 2; i++) {
        size_t n = (size_t)(n0 + 2 * i);
        out[n * C + c]       = acc[i].x;
        out[(n + 1) * C + c] = acc[i].y;
    }
}

// ---------------- launch ----------------
extern "C" void kernel_launch(void* const* d_in, const int* in_sizes, int n_in,
                              void* d_out, int out_size) {
    const float* feats = (const float*)d_in[0];
    const float* npts  = (const float*)d_in[1];
    const float* Wq    = (const float*)d_in[2];
    const float* bq    = (const float*)d_in[3];
    const float* Wv    = (const float*)d_in[4];
    const float* bv    = (const float*)d_in[5];
    const float* Wo    = (const float*)d_in[6];
    const float* bo    = (const float*)d_in[7];
    const float* pe    = (const float*)d_in[8];
    const float* W1    = (const float*)d_in[9];
    const float* g1    = (const float*)d_in[10];
    const float* b1    = (const float*)d_in[11];
    const float* m1    = (const float*)d_in[12];
    const float* v1    = (const float*)d_in[13];
    const float* W2    = (const float*)d_in[14];
    const float* g2    = (const float*)d_in[15];
    const float* b2    = (const float*)d_in[16];
    const float* m2    = (const float*)d_in[17];
    const float* v2    = (const float*)d_in[18];
    const float* W3    = (const float*)d_in[19];
    const float* b3    = (const float*)d_in[20];
    const int* qi      = (const int*)d_in[21];
    const int* ki      = (const int*)d_in[22];
    const int* kk      = (const int*)d_in[23];

    const int M = in_sizes[21];
    const int n = in_sizes[0] / C;   // 131072

    prep_small<<<1, 256>>>(W1, g1, b1, m1, v1, W2, g2, b2, m2, v2, pe);
    prep_fold<<<C + 1, 128>>>(W3, b3, Wq, bq, Wv, bv);
    zero_acc<<<(NPTS * C / 4 + 255) / 256, 256>>>();
    qv_kernel<<<n / TP, 128>>>(feats, npts, Wq, Wv);
    attn_scatter<<<2048, 256>>>(qi, ki, kk, M);
    out_kernel<<<n / TP, 128>>>(Wo, bo, (float*)d_out);
}

// round 3
// speedup vs baseline: 1.0124x; 1.0124x over previous
#include <cuda_runtime.h>
#include <cstdint>

// Problem constants (FastPointTransformer)
#define NPTS 131072
#define C    128
#define NH   8
#define DD   16
#define KK   27
#define TP   32          // points per block in GEMM kernels
#define SPAD 36          // smem row stride (floats): 144B = 16B-aligned rows

// ---------------- device scratch (no allocs allowed) ----------------
__device__ __align__(256) float g_nq [NPTS * C];        // normalized q   [N,128]
__device__ __align__(256) float g_v  [NPTS * C];        // v              [N,128]
__device__ __align__(256) float g_acc[NPTS * C];        // attention out  [N,128]
__device__ __align__(256) float g_att[(size_t)NPTS * KK * NH]; // attn table [N,27,8]
__device__ float g_W3q[C * C];
__device__ float g_W3v[C * C];
__device__ float g_bq2[C];
__device__ float g_bv2[C];
__device__ float g_W2f[3 * C];
__device__ float g_t2[C];
__device__ float g_W1f[9];
__device__ float g_t1[3];
__device__ __align__(16) float g_npe[KK * C];           // normalized pos enc

// ---------------- packed f32x2 FMA (Blackwell; ptxas won't auto-fuse) ----------------
__device__ __forceinline__ float2 ffma2(float2 a, float2 b, float2 c) {
    float2 d;
    asm("{\n\t"
        ".reg .b64 A,B,Cr,Dr;\n\t"
        "mov.b64 A, {%2,%3};\n\t"
        "mov.b64 B, {%4,%5};\n\t"
        "mov.b64 Cr, {%6,%7};\n\t"
        "fma.rn.f32x2 Dr, A, B, Cr;\n\t"
        "mov.b64 {%0,%1}, Dr;\n\t"
        "}"
        : "=f"(d.x), "=f"(d.y)
        : "f"(a.x), "f"(a.y), "f"(b.x), "f"(b.y), "f"(c.x), "f"(c.y));
    return d;
}
__device__ __forceinline__ float2 bc2(float w) { return make_float2(w, w); }

// ---------------- prep: fold BN into affine, normalize pos enc ----------------
__global__ void prep_small(const float* __restrict__ W1, const float* __restrict__ g1,
                           const float* __restrict__ b1, const float* __restrict__ m1,
                           const float* __restrict__ v1,
                           const float* __restrict__ W2, const float* __restrict__ g2,
                           const float* __restrict__ b2, const float* __restrict__ m2,
                           const float* __restrict__ v2,
                           const float* __restrict__ pe) {
    int t = threadIdx.x;  // 256 threads
    if (t < 3) {
        float s = g1[t] * rsqrtf(v1[t] + 1e-5f);
        g_t1[t] = b1[t] - m1[t] * s;
    }
    if (t < 9) {
        int j = t % 3;
        float s = g1[j] * rsqrtf(v1[j] + 1e-5f);
        g_W1f[t] = W1[t] * s;
    }
    if (t < C) {
        float s = g2[t] * rsqrtf(v2[t] + 1e-5f);
        g_t2[t] = b2[t] - m2[t] * s;
        for (int i = 0; i < 3; i++) g_W2f[i * C + t] = W2[i * C + t] * s;
    }
    // normalize inter_pos_enc rows (K*H groups of D)
    for (int g = t; g < KK * NH; g += blockDim.x) {
        float vals[DD];
        float ss = 0.f;
        for (int d = 0; d < DD; d++) { vals[d] = pe[g * DD + d]; ss += vals[d] * vals[d]; }
        float sc = 1.f / fmaxf(sqrtf(ss), 1e-12f);
        for (int d = 0; d < DD; d++) g_npe[g * DD + d] = vals[d] * sc;
    }
}

// Fold W3 into Wq/Wv: W3q = W3@Wq, bq2 = bq + b3@Wq (block 128 handles biases)
__global__ void prep_fold(const float* __restrict__ W3, const float* __restrict__ b3,
                          const float* __restrict__ Wq, const float* __restrict__ bq,
                          const float* __restrict__ Wv, const float* __restrict__ bv) {
    __shared__ float srow[C];
    int k = blockIdx.x, c = threadIdx.x;
    srow[c] = (k < C) ? W3[k * C + c] : b3[c];
    __syncthreads();
    float aq = 0.f, av = 0.f;
#pragma unroll 4
    for (int j = 0; j < C; j++) {
        float s = srow[j];
        aq = fmaf(s, Wq[j * C + c], aq);
        av = fmaf(s, Wv[j * C + c], av);
    }
    if (k < C) { g_W3q[k * C + c] = aq; g_W3v[k * C + c] = av; }
    else       { g_bq2[c] = bq[c] + aq; g_bv2[c] = bv[c] + av; }
}

__global__ void zero_acc() {
    int i = blockIdx.x * blockDim.x + threadIdx.x;
    if (i < NPTS * C / 4) reinterpret_cast<float4*>(g_acc)[i] = make_float4(0.f, 0.f, 0.f, 0.f);
}

// ---------------- fused MLP + Q/V GEMM (K=256) + per-head L2 norm ----------------
__global__ __launch_bounds__(128) void qv_kernel(const float* __restrict__ feats,
                                                 const float* __restrict__ npts,
                                                 const float* __restrict__ Wq,
                                                 const float* __restrict__ Wv) {
    __shared__ __align__(16) float sf[C][SPAD];   // feats^T (rows 16B-aligned)
    __shared__ __align__(16) float sh[C][SPAD];   // h2^T
    __shared__ float sh1[TP][3];

    const int c = threadIdx.x;
    const int n0 = blockIdx.x * TP;

#pragma unroll
    for (int p = 0; p < TP; p++) sf[c][p] = feats[(size_t)(n0 + p) * C + c];

    if (c < TP) {
        float p0 = npts[(size_t)(n0 + c) * 3 + 0];
        float p1 = npts[(size_t)(n0 + c) * 3 + 1];
        float p2 = npts[(size_t)(n0 + c) * 3 + 2];
#pragma unroll
        for (int j = 0; j < 3; j++) {
            float h = p0 * g_W1f[j] + p1 * g_W1f[3 + j] + p2 * g_W1f[6 + j] + g_t1[j];
            sh1[c][j] = fmaxf(h, 0.f);
        }
    }
    __syncthreads();

    {
        float w0 = g_W2f[c], w1 = g_W2f[C + c], w2 = g_W2f[2 * C + c], tt = g_t2[c];
#pragma unroll
        for (int p = 0; p < TP; p++)
            sh[c][p] = fmaxf(sh1[p][0] * w0 + sh1[p][1] * w1 + sh1[p][2] * w2 + tt, 0.f);
    }
    __syncthreads();

    float bq0 = g_bq2[c], bv0 = g_bv2[c];
    float2 aq[TP / 2], av[TP / 2];
#pragma unroll
    for (int i = 0; i < TP / 2; i++) { aq[i] = make_float2(bq0, bq0); av[i] = make_float2(bv0, bv0); }

#pragma unroll 2
    for (int k = 0; k < C; k++) {
        float2 wq  = bc2(Wq[k * C + c]);
        float2 wv  = bc2(Wv[k * C + c]);
        float2 w3q = bc2(g_W3q[k * C + c]);
        float2 w3v = bc2(g_W3v[k * C + c]);
        const float4* f4 = reinterpret_cast<const float4*>(&sf[k][0]);
        const float4* h4 = reinterpret_cast<const float4*>(&sh[k][0]);
#pragma unroll
        for (int i = 0; i < TP / 4; i++) {
            float4 f = f4[i];
            float4 h = h4[i];
            float2 flo = make_float2(f.x, f.y), fhi = make_float2(f.z, f.w);
            float2 hlo = make_float2(h.x, h.y), hhi = make_float2(h.z, h.w);
            aq[2 * i]     = ffma2(flo, wq,  aq[2 * i]);
            aq[2 * i]     = ffma2(hlo, w3q, aq[2 * i]);
            aq[2 * i + 1] = ffma2(fhi, wq,  aq[2 * i + 1]);
            aq[2 * i + 1] = ffma2(hhi, w3q, aq[2 * i + 1]);
            av[2 * i]     = ffma2(flo, wv,  av[2 * i]);
            av[2 * i]     = ffma2(hlo, w3v, av[2 * i]);
            av[2 * i + 1] = ffma2(fhi, wv,  av[2 * i + 1]);
            av[2 * i + 1] = ffma2(hhi, w3v, av[2 * i + 1]);
        }
    }

    // per-head (16-lane) L2 norm of q; write nq and v
#pragma unroll
    for (int i = 0; i < TP / 2; i++) {
        float sx = aq[i].x * aq[i].x;
        float sy = aq[i].y * aq[i].y;
#pragma unroll
        for (int off = 8; off > 0; off >>= 1) {
            sx += __shfl_xor_sync(0xffffffffu, sx, off);
            sy += __shfl_xor_sync(0xffffffffu, sy, off);
        }
        float scx = 1.f / fmaxf(sqrtf(sx), 1e-12f);
        float scy = 1.f / fmaxf(sqrtf(sy), 1e-12f);
        size_t n = (size_t)(n0 + 2 * i);
        g_nq[n * C + c]       = aq[i].x * scx;
        g_nq[(n + 1) * C + c] = aq[i].y * scy;
        g_v [n * C + c]       = av[i].x;
        g_v [(n + 1) * C + c] = av[i].y;
    }
}

// ---------------- attn table: att[n][k][h] = <nq[n,h,:], npe[k,h,:]> ----------------
__global__ __launch_bounds__(256) void att_kernel() {
    __shared__ __align__(16) float s_npe[KK * C];
    for (int i = threadIdx.x; i < KK * C; i += 256) s_npe[i] = g_npe[i];
    __syncthreads();

    const int lane   = threadIdx.x & 31;
    const int warp   = (blockIdx.x * 256 + threadIdx.x) >> 5;
    const int nwarps = (gridDim.x * 256) >> 5;
    const int h      = lane >> 2;
    const bool wr    = (lane & 3) == 0;

    for (int n = warp; n < NPTS; n += nwarps) {
        float4 a = reinterpret_cast<const float4*>(g_nq + (size_t)n * C)[lane];
        float* dst = g_att + ((size_t)n * KK) * NH + h;
#pragma unroll
        for (int k = 0; k < KK; k++) {
            float4 b = *reinterpret_cast<const float4*>(s_npe + k * C + lane * 4);
            float p = a.x * b.x + a.y * b.y + a.z * b.z + a.w * b.w;
            p += __shfl_xor_sync(0xffffffffu, p, 1);
            p += __shfl_xor_sync(0xffffffffu, p, 2);
            if (wr) dst[k * NH] = p;
        }
    }
}

// ---------------- fused scatter: out[q] += att[q,kk,h] * v[key] ----------------
__global__ __launch_bounds__(256) void attn_scatter(const int* __restrict__ qidx,
                                                    const int* __restrict__ kidx,
                                                    const int* __restrict__ kern,
                                                    int M) {
    const int lane   = threadIdx.x & 31;
    const int warp   = (blockIdx.x * 256 + threadIdx.x) >> 5;
    const int nwarps = (gridDim.x * 256) >> 5;
    const int h      = lane >> 2;

    for (int m = warp; m < M; m += nwarps) {
        int q   = __ldg(qidx + m);
        int key = __ldg(kidx + m);
        int kk  = __ldg(kern + m);

        float a = __ldg(g_att + ((size_t)q * KK + kk) * NH + h);
        float4 vv = reinterpret_cast<const float4*>(g_v + (size_t)key * C)[lane];
        float* dst = g_acc + (size_t)q * C + lane * 4;
        asm volatile("red.global.add.v4.f32 [%0], {%1,%2,%3,%4};"
                     :: "l"(dst), "f"(a * vv.x), "f"(a * vv.y),
                        "f"(a * vv.z), "f"(a * vv.w)
                     : "memory");
    }
}

// ---------------- epilogue GEMM: out = acc @ Wo + bo ----------------
__global__ __launch_bounds__(128) void out_kernel(const float* __restrict__ Wo,
                                                  const float* __restrict__ bo,
                                                  float* __restrict__ out) {
    __shared__ __align__(16) float sa[C][SPAD];
    const int c = threadIdx.x;
    const int n0 = blockIdx.x * TP;

#pragma unroll
    for (int p = 0; p < TP; p++) sa[c][p] = g_acc[(size_t)(n0 + p) * C + c];
    __syncthreads();

    float b = bo[c];
    float2 acc[TP / 2];
#pragma unroll
    for (int i = 0; i < TP / 2; i++) acc[i] = make_float2(b, b);

#pragma unroll 2
    for (int k = 0; k < C; k++) {
        float2 w = bc2(Wo[k * C + c]);
        const float4* a4 = reinterpret_cast<const float4*>(&sa[k][0]);
#pragma unroll
        for (int i = 0; i < TP / 4; i++) {
            float4 f = a4[i];
            acc[2 * i]     = ffma2(make_float2(f.x, f.y), w, acc[2 * i]);
            acc[2 * i + 1] = ffma2(make_float2(f.z, f.w), w, acc[2 * i + 1]);
        }
    }
#pragma unroll
    for (int i = 0; i < TP / 2; i++) {
        size_t n = (size_t)(n0 + 2 * i);
        out[n * C + c]       = acc[i].x;
        out[(n + 1) * C + c] = acc[i].y;
    }
}

// ---------------- launch ----------------
extern "C" void kernel_launch(void* const* d_in, const int* in_sizes, int n_in,
                              void* d_out, int out_size) {
    const float* feats = (const float*)d_in[0];
    const float* npts  = (const float*)d_in[1];
    const float* Wq    = (const float*)d_in[2];
    const float* bq    = (const float*)d_in[3];
    const float* Wv    = (const float*)d_in[4];
    const float* bv    = (const float*)d_in[5];
    const float* Wo    = (const float*)d_in[6];
    const float* bo    = (const float*)d_in[7];
    const float* pe    = (const float*)d_in[8];
    const float* W1    = (const float*)d_in[9];
    const float* g1    = (const float*)d_in[10];
    const float* b1    = (const float*)d_in[11];
    const float* m1    = (const float*)d_in[12];
    const float* v1    = (const float*)d_in[13];
    const float* W2    = (const float*)d_in[14];
    const float* g2    = (const float*)d_in[15];
    const float* b2    = (const float*)d_in[16];
    const float* m2    = (const float*)d_in[17];
    const float* v2    = (const float*)d_in[18];
    const float* W3    = (const float*)d_in[19];
    const float* b3    = (const float*)d_in[20];
    const int* qi      = (const int*)d_in[21];
    const int* ki      = (const int*)d_in[22];
    const int* kk      = (const int*)d_in[23];

    const int M = in_sizes[21];
    const int n = in_sizes[0] / C;   // 131072

    prep_small<<<1, 256>>>(W1, g1, b1, m1, v1, W2, g2, b2, m2, v2, pe);
    prep_fold<<<C + 1, 128>>>(W3, b3, Wq, bq, Wv, bv);
    zero_acc<<<(NPTS * C / 4 + 255) / 256, 256>>>();
    qv_kernel<<<n / TP, 128>>>(feats, npts, Wq, Wv);
    att_kernel<<<1024, 256>>>();
    attn_scatter<<<2368, 256>>>(qi, ki, kk, M);
    out_kernel<<<n / TP, 128>>>(Wo, bo, (float*)d_out);
}

// round 4
// speedup vs baseline: 1.2912x; 1.2754x over previous
#include <cuda_runtime.h>
#include <cstdint>

// Problem constants (FastPointTransformer)
#define NPTS 131072
#define C    128
#define NH   8
#define DD   16
#define KK   27
#define TP   32          // points per block in GEMM kernels
#define SPAD 36          // smem row stride (floats): 144B = 16B-aligned rows
#define MMAX 2097152     // M (pairs)

// ---------------- device scratch (no allocs allowed) ----------------
__device__ __align__(256) float g_nq [NPTS * C];        // normalized q   [N,128]
__device__ __align__(256) float g_v  [NPTS * C];        // v              [N,128]
__device__ __align__(256) float g_acc[NPTS * C];        // attention out  [N,128]
__device__ float g_W3q[C * C];
__device__ float g_W3v[C * C];
__device__ float g_bq2[C];
__device__ float g_bv2[C];
__device__ float g_W2f[3 * C];
__device__ float g_t2[C];
__device__ float g_W1f[9];
__device__ float g_t1[3];
__device__ __align__(16) float g_npe[KK * C];           // normalized pos enc

// sort scratch
__device__ __align__(256) int2 g_sp[MMAX];              // sorted (key, kernel) pairs
__device__ int g_cnt [NPTS];
__device__ int g_part[NPTS];                            // intra-block exclusive scan
__device__ int g_start[NPTS];                           // final exclusive offsets
__device__ int g_cur [NPTS];                            // placement cursors
__device__ int g_bsum[NPTS / 1024];                     // per-scan-block sums
__device__ int g_boff[NPTS / 1024];                     // scanned block sums

// ---------------- packed f32x2 FMA (Blackwell; ptxas won't auto-fuse) ----------------
__device__ __forceinline__ float2 ffma2(float2 a, float2 b, float2 c) {
    float2 d;
    asm("{\n\t"
        ".reg .b64 A,B,Cr,Dr;\n\t"
        "mov.b64 A, {%2,%3};\n\t"
        "mov.b64 B, {%4,%5};\n\t"
        "mov.b64 Cr, {%6,%7};\n\t"
        "fma.rn.f32x2 Dr, A, B, Cr;\n\t"
        "mov.b64 {%0,%1}, Dr;\n\t"
        "}"
        : "=f"(d.x), "=f"(d.y)
        : "f"(a.x), "f"(a.y), "f"(b.x), "f"(b.y), "f"(c.x), "f"(c.y));
    return d;
}
__device__ __forceinline__ float2 bc2(float w) { return make_float2(w, w); }

// ---------------- prep: fold BN into affine, normalize pos enc ----------------
__global__ void prep_small(const float* __restrict__ W1, const float* __restrict__ g1,
                           const float* __restrict__ b1, const float* __restrict__ m1,
                           const float* __restrict__ v1,
                           const float* __restrict__ W2, const float* __restrict__ g2,
                           const float* __restrict__ b2, const float* __restrict__ m2,
                           const float* __restrict__ v2,
                           const float* __restrict__ pe) {
    int t = threadIdx.x;  // 256 threads
    if (t < 3) {
        float s = g1[t] * rsqrtf(v1[t] + 1e-5f);
        g_t1[t] = b1[t] - m1[t] * s;
    }
    if (t < 9) {
        int j = t % 3;
        float s = g1[j] * rsqrtf(v1[j] + 1e-5f);
        g_W1f[t] = W1[t] * s;
    }
    if (t < C) {
        float s = g2[t] * rsqrtf(v2[t] + 1e-5f);
        g_t2[t] = b2[t] - m2[t] * s;
        for (int i = 0; i < 3; i++) g_W2f[i * C + t] = W2[i * C + t] * s;
    }
    // normalize inter_pos_enc rows (K*H groups of D)
    for (int g = t; g < KK * NH; g += blockDim.x) {
        float vals[DD];
        float ss = 0.f;
        for (int d = 0; d < DD; d++) { vals[d] = pe[g * DD + d]; ss += vals[d] * vals[d]; }
        float sc = 1.f / fmaxf(sqrtf(ss), 1e-12f);
        for (int d = 0; d < DD; d++) g_npe[g * DD + d] = vals[d] * sc;
    }
}

// Fold W3 into Wq/Wv: W3q = W3@Wq, bq2 = bq + b3@Wq (block 128 handles biases)
__global__ void prep_fold(const float* __restrict__ W3, const float* __restrict__ b3,
                          const float* __restrict__ Wq, const float* __restrict__ bq,
                          const float* __restrict__ Wv, const float* __restrict__ bv) {
    __shared__ float srow[C];
    int k = blockIdx.x, c = threadIdx.x;
    srow[c] = (k < C) ? W3[k * C + c] : b3[c];
    __syncthreads();
    float aq = 0.f, av = 0.f;
#pragma unroll 4
    for (int j = 0; j < C; j++) {
        float s = srow[j];
        aq = fmaf(s, Wq[j * C + c], aq);
        av = fmaf(s, Wv[j * C + c], av);
    }
    if (k < C) { g_W3q[k * C + c] = aq; g_W3v[k * C + c] = av; }
    else       { g_bq2[c] = bq[c] + aq; g_bv2[c] = bv[c] + av; }
}

// ---------------- fused MLP + Q/V GEMM (K=256) + per-head L2 norm ----------------
__global__ __launch_bounds__(128) void qv_kernel(const float* __restrict__ feats,
                                                 const float* __restrict__ npts,
                                                 const float* __restrict__ Wq,
                                                 const float* __restrict__ Wv) {
    __shared__ __align__(16) float sf[C][SPAD];   // feats^T (rows 16B-aligned)
    __shared__ __align__(16) float sh[C][SPAD];   // h2^T
    __shared__ float sh1[TP][3];

    const int c = threadIdx.x;
    const int n0 = blockIdx.x * TP;

#pragma unroll
    for (int p = 0; p < TP; p++) sf[c][p] = feats[(size_t)(n0 + p) * C + c];

    if (c < TP) {
        float p0 = npts[(size_t)(n0 + c) * 3 + 0];
        float p1 = npts[(size_t)(n0 + c) * 3 + 1];
        float p2 = npts[(size_t)(n0 + c) * 3 + 2];
#pragma unroll
        for (int j = 0; j < 3; j++) {
            float h = p0 * g_W1f[j] + p1 * g_W1f[3 + j] + p2 * g_W1f[6 + j] + g_t1[j];
            sh1[c][j] = fmaxf(h, 0.f);
        }
    }
    __syncthreads();

    {
        float w0 = g_W2f[c], w1 = g_W2f[C + c], w2 = g_W2f[2 * C + c], tt = g_t2[c];
#pragma unroll
        for (int p = 0; p < TP; p++)
            sh[c][p] = fmaxf(sh1[p][0] * w0 + sh1[p][1] * w1 + sh1[p][2] * w2 + tt, 0.f);
    }
    __syncthreads();

    float bq0 = g_bq2[c], bv0 = g_bv2[c];
    float2 aq[TP / 2], av[TP / 2];
#pragma unroll
    for (int i = 0; i < TP / 2; i++) { aq[i] = make_float2(bq0, bq0); av[i] = make_float2(bv0, bv0); }

#pragma unroll 2
    for (int k = 0; k < C; k++) {
        float2 wq  = bc2(Wq[k * C + c]);
        float2 wv  = bc2(Wv[k * C + c]);
        float2 w3q = bc2(g_W3q[k * C + c]);
        float2 w3v = bc2(g_W3v[k * C + c]);
        const float4* f4 = reinterpret_cast<const float4*>(&sf[k][0]);
        const float4* h4 = reinterpret_cast<const float4*>(&sh[k][0]);
#pragma unroll
        for (int i = 0; i < TP / 4; i++) {
            float4 f = f4[i];
            float4 h = h4[i];
            float2 flo = make_float2(f.x, f.y), fhi = make_float2(f.z, f.w);
            float2 hlo = make_float2(h.x, h.y), hhi = make_float2(h.z, h.w);
            aq[2 * i]     = ffma2(flo, wq,  aq[2 * i]);
            aq[2 * i]     = ffma2(hlo, w3q, aq[2 * i]);
            aq[2 * i + 1] = ffma2(fhi, wq,  aq[2 * i + 1]);
            aq[2 * i + 1] = ffma2(hhi, w3q, aq[2 * i + 1]);
            av[2 * i]     = ffma2(flo, wv,  av[2 * i]);
            av[2 * i]     = ffma2(hlo, w3v, av[2 * i]);
            av[2 * i + 1] = ffma2(fhi, wv,  av[2 * i + 1]);
            av[2 * i + 1] = ffma2(hhi, w3v, av[2 * i + 1]);
        }
    }

    // per-head (16-lane) L2 norm of q; write nq and v
#pragma unroll
    for (int i = 0; i < TP / 2; i++) {
        float sx = aq[i].x * aq[i].x;
        float sy = aq[i].y * aq[i].y;
#pragma unroll
        for (int off = 8; off > 0; off >>= 1) {
            sx += __shfl_xor_sync(0xffffffffu, sx, off);
            sy += __shfl_xor_sync(0xffffffffu, sy, off);
        }
        float scx = 1.f / fmaxf(sqrtf(sx), 1e-12f);
        float scy = 1.f / fmaxf(sqrtf(sy), 1e-12f);
        size_t n = (size_t)(n0 + 2 * i);
        g_nq[n * C + c]       = aq[i].x * scx;
        g_nq[(n + 1) * C + c] = aq[i].y * scy;
        g_v [n * C + c]       = av[i].x;
        g_v [(n + 1) * C + c] = av[i].y;
    }
}

// ---------------- counting sort by query ----------------
__global__ void k_zero_cnt() {
    int i = blockIdx.x * blockDim.x + threadIdx.x;
    if (i < NPTS) g_cnt[i] = 0;
}

__global__ void k_hist(const int* __restrict__ qidx, int M) {
    int i = blockIdx.x * blockDim.x + threadIdx.x;
    int stride = gridDim.x * blockDim.x;
    for (int m = i; m < M; m += stride) atomicAdd(&g_cnt[__ldg(qidx + m)], 1);
}

// 1024-elem block scans (exclusive) + block totals. 128 blocks x 1024 threads.
__global__ __launch_bounds__(1024) void k_scan1() {
    __shared__ int s[1024];
    int i = blockIdx.x * 1024 + threadIdx.x;
    int val = g_cnt[i];
    s[threadIdx.x] = val;
    __syncthreads();
    int acc = val;
#pragma unroll
    for (int off = 1; off < 1024; off <<= 1) {
        int t = (threadIdx.x >= off) ? s[threadIdx.x - off] : 0;
        __syncthreads();
        acc += t;
        s[threadIdx.x] = acc;
        __syncthreads();
    }
    g_part[i] = acc - val;                       // exclusive
    if (threadIdx.x == 1023) g_bsum[blockIdx.x] = acc;
}

__global__ void k_scan2() {  // 1 thread, 128 elems — trivial
    if (threadIdx.x == 0) {
        int run = 0;
        for (int b = 0; b < NPTS / 1024; b++) { g_boff[b] = run; run += g_bsum[b]; }
    }
}

__global__ void k_scan3() {
    int i = blockIdx.x * blockDim.x + threadIdx.x;
    if (i < NPTS) {
        int st = g_part[i] + g_boff[i >> 10];
        g_start[i] = st;
        g_cur[i]   = st;
    }
}

__global__ void k_place(const int* __restrict__ qidx, const int* __restrict__ kidx,
                        const int* __restrict__ kern, int M) {
    int i = blockIdx.x * blockDim.x + threadIdx.x;
    int stride = gridDim.x * blockDim.x;
    for (int m = i; m < M; m += stride) {
        int q = __ldg(qidx + m);
        int pos = atomicAdd(&g_cur[q], 1);
        g_sp[pos] = make_int2(__ldg(kidx + m), __ldg(kern + m));
    }
}

// ---------------- per-query gather + on-the-fly attention + register accumulate ----------------
__global__ __launch_bounds__(256) void gather_acc() {
    __shared__ __align__(16) float s_npe[KK * C];
    for (int i = threadIdx.x; i < KK * C; i += 256) s_npe[i] = g_npe[i];
    __syncthreads();

    const int lane    = threadIdx.x & 31;
    const int warp    = (blockIdx.x * 256 + threadIdx.x) >> 5;
    const int nwarps  = (gridDim.x * 256) >> 5;
    const float4* v4  = reinterpret_cast<const float4*>(g_v);
    const float4* nq4 = reinterpret_cast<const float4*>(g_nq);
    const float4* pe4 = reinterpret_cast<const float4*>(s_npe);

    for (int q = warp; q < NPTS; q += nwarps) {
        int s = g_start[q];
        int n = g_cnt[q];
        float4 aqv = nq4[(size_t)q * 32 + lane];   // this lane's nq quad (row resident)
        float4 acc = make_float4(0.f, 0.f, 0.f, 0.f);

        for (int base = 0; base < n; base += 32) {
            int take = n - base; if (take > 32) take = 32;
            int2 pl = (lane < take) ? g_sp[s + base + lane] : make_int2(0, 0);
            int j = 0;
#pragma unroll 4
            for (; j < take; j++) {
                int key = __shfl_sync(0xffffffffu, pl.x, j);
                int kk  = __shfl_sync(0xffffffffu, pl.y, j);
                float4 b = pe4[kk * 32 + lane];
                float part = aqv.x * b.x + aqv.y * b.y + aqv.z * b.z + aqv.w * b.w;
                part += __shfl_xor_sync(0xffffffffu, part, 1);
                part += __shfl_xor_sync(0xffffffffu, part, 2);
                float4 vv = v4[(size_t)key * 32 + lane];
                acc.x = fmaf(part, vv.x, acc.x);
                acc.y = fmaf(part, vv.y, acc.y);
                acc.z = fmaf(part, vv.z, acc.z);
                acc.w = fmaf(part, vv.w, acc.w);
            }
        }
        reinterpret_cast<float4*>(g_acc)[(size_t)q * 32 + lane] = acc;
    }
}

// ---------------- epilogue GEMM: out = acc @ Wo + bo ----------------
__global__ __launch_bounds__(128) void out_kernel(const float* __restrict__ Wo,
                                                  const float* __restrict__ bo,
                                                  float* __restrict__ out) {
    __shared__ __align__(16) float sa[C][SPAD];
    const int c = threadIdx.x;
    const int n0 = blockIdx.x * TP;

#pragma unroll
    for (int p = 0; p < TP; p++) sa[c][p] = g_acc[(size_t)(n0 + p) * C + c];
    __syncthreads();

    float b = bo[c];
    float2 acc[TP / 2];
#pragma unroll
    for (int i = 0; i < TP / 2; i++) acc[i] = make_float2(b, b);

#pragma unroll 2
    for (int k = 0; k < C; k++) {
        float2 w = bc2(Wo[k * C + c]);
        const float4* a4 = reinterpret_cast<const float4*>(&sa[k][0]);
#pragma unroll
        for (int i = 0; i < TP / 4; i++) {
            float4 f = a4[i];
            acc[2 * i]     = ffma2(make_float2(f.x, f.y), w, acc[2 * i]);
            acc[2 * i + 1] = ffma2(make_float2(f.z, f.w), w, acc[2 * i + 1]);
        }
    }
#pragma unroll
    for (int i = 0; i < TP / 2; i++) {
        size_t n = (size_t)(n0 + 2 * i);
        out[n * C + c]       = acc[i].x;
        out[(n + 1) * C + c] = acc[i].y;
    }
}

// ---------------- launch ----------------
extern "C" void kernel_launch(void* const* d_in, const int* in_sizes, int n_in,
                              void* d_out, int out_size) {
    const float* feats = (const float*)d_in[0];
    const float* npts  = (const float*)d_in[1];
    const float* Wq    = (const float*)d_in[2];
    const float* bq    = (const float*)d_in[3];
    const float* Wv    = (const float*)d_in[4];
    const float* bv    = (const float*)d_in[5];
    const float* Wo    = (const float*)d_in[6];
    const float* bo    = (const float*)d_in[7];
    const float* pe    = (const float*)d_in[8];
    const float* W1    = (const float*)d_in[9];
    const float* g1    = (const float*)d_in[10];
    const float* b1    = (const float*)d_in[11];
    const float* m1    = (const float*)d_in[12];
    const float* v1    = (const float*)d_in[13];
    const float* W2    = (const float*)d_in[14];
    const float* g2    = (const float*)d_in[15];
    const float* b2    = (const float*)d_in[16];
    const float* m2    = (const float*)d_in[17];
    const float* v2    = (const float*)d_in[18];
    const float* W3    = (const float*)d_in[19];
    const float* b3    = (const float*)d_in[20];
    const int* qi      = (const int*)d_in[21];
    const int* ki      = (const int*)d_in[22];
    const int* kk      = (const int*)d_in[23];

    const int M = in_sizes[21];
    const int n = in_sizes[0] / C;   // 131072

    prep_small<<<1, 256>>>(W1, g1, b1, m1, v1, W2, g2, b2, m2, v2, pe);
    prep_fold<<<C + 1, 128>>>(W3, b3, Wq, bq, Wv, bv);
    qv_kernel<<<n / TP, 128>>>(feats, npts, Wq, Wv);

    // counting sort by query
    k_zero_cnt<<<(NPTS + 255) / 256, 256>>>();
    k_hist<<<1024, 256>>>(qi, M);
    k_scan1<<<NPTS / 1024, 1024>>>();
    k_scan2<<<1, 32>>>();
    k_scan3<<<(NPTS + 255) / 256, 256>>>();
    k_place<<<1024, 256>>>(qi, ki, kk, M);

    gather_acc<<<2048, 256>>>();
    out_kernel<<<n / TP, 128>>>(Wo, bo, (float*)d_out);
}

// round 6
// speedup vs baseline: 1.7179x; 1.3304x over previous
#include <cuda_runtime.h>
#include <cuda_bf16.h>
#include <cstdint>

// Problem constants (FastPointTransformer)
#define NPTS 131072
#define C    128
#define NH   8
#define DD   16
#define KK   27
#define TP   32          // points per block in out_kernel
#define SPAD 36          // smem row stride (floats) in out_kernel
#define MMAX 2097152     // M (pairs)

// mma.sync GEMM geometry: CTA = 64 points x 256 outs (q||v), K=256 in 4 chunks of 64
#define MT    64         // points per CTA
#define KC    64         // k per chunk
#define NCH   4          // chunks
#define BPAD  72         // smem row stride in bf16 (144B, 16B aligned, conflict-free ldmatrix)

// dynamic smem layout (bytes)
#define SA_HI 0
#define SA_LO 9216              // 64*72*2
#define SB_HI 18432
#define SB_LO 55296             // + 256*72*2
#define SBIAS 92160             // 256 floats
#define SW2O  93184             // 384 floats
#define ST2O  94720             // 128 floats
#define SH1O  95232             // 64*3 floats
#define QV_SMEM 96256

// ---------------- device scratch (no allocs allowed) ----------------
__device__ __align__(256) float g_nq [NPTS * C];        // normalized q
__device__ __align__(256) float g_v  [NPTS * C];        // v
__device__ __align__(256) float g_acc[NPTS * C];        // attention out
__device__ float g_W3q[C * C];
__device__ float g_W3v[C * C];
__device__ float g_bq2[C];
__device__ float g_bv2[C];
__device__ float g_W2f[3 * C];
__device__ float g_t2[C];
__device__ float g_W1f[9];
__device__ float g_t1[3];
__device__ __align__(16) float g_npe[KK * C];

// bf16 weight images: [chunk][n=256][k=64], n: 0-127 q, 128-255 v
__device__ __align__(16) unsigned short g_Bhi[NCH * 256 * KC];
__device__ __align__(16) unsigned short g_Blo[NCH * 256 * KC];

// sort scratch
__device__ __align__(256) int2 g_sp[MMAX];
__device__ int g_cnt [NPTS];
__device__ int g_part[NPTS];
__device__ int g_start[NPTS];
__device__ int g_cur [NPTS];
__device__ int g_bsum[NPTS / 1024];
__device__ int g_boff[NPTS / 1024];

// ---------------- packed f32x2 FMA ----------------
__device__ __forceinline__ float2 ffma2(float2 a, float2 b, float2 c) {
    float2 d;
    asm("{\n\t"
        ".reg .b64 A,B,Cr,Dr;\n\t"
        "mov.b64 A, {%2,%3};\n\t"
        "mov.b64 B, {%4,%5};\n\t"
        "mov.b64 Cr, {%6,%7};\n\t"
        "fma.rn.f32x2 Dr, A, B, Cr;\n\t"
        "mov.b64 {%0,%1}, Dr;\n\t"
        "}"
        : "=f"(d.x), "=f"(d.y)
        : "f"(a.x), "f"(a.y), "f"(b.x), "f"(b.y), "f"(c.x), "f"(c.y));
    return d;
}
__device__ __forceinline__ float2 bc2(float w) { return make_float2(w, w); }

__device__ __forceinline__ uint32_t smem_u32(const void* p) {
    uint32_t a;
    asm("{ .reg .u64 t; cvta.to.shared.u64 t, %1; cvt.u32.u64 %0, t; }" : "=r"(a) : "l"(p));
    return a;
}
__device__ __forceinline__ void ldmx4(uint32_t& r0, uint32_t& r1, uint32_t& r2, uint32_t& r3, uint32_t a) {
    asm volatile("ldmatrix.sync.aligned.m8n8.x4.shared.b16 {%0,%1,%2,%3}, [%4];"
                 : "=r"(r0), "=r"(r1), "=r"(r2), "=r"(r3) : "r"(a));
}
__device__ __forceinline__ void mma16816(float* c, uint32_t a0, uint32_t a1, uint32_t a2, uint32_t a3,
                                         uint32_t b0, uint32_t b1) {
    asm volatile("mma.sync.aligned.m16n8k16.row.col.f32.bf16.bf16.f32 "
                 "{%0,%1,%2,%3}, {%4,%5,%6,%7}, {%8,%9}, {%0,%1,%2,%3};"
                 : "+f"(c[0]), "+f"(c[1]), "+f"(c[2]), "+f"(c[3])
                 : "r"(a0), "r"(a1), "r"(a2), "r"(a3), "r"(b0), "r"(b1));
}

// split one float into bf16 hi + residual-lo
__device__ __forceinline__ void split1(float x, unsigned short& h, unsigned short& l) {
    __nv_bfloat16 hb = __float2bfloat16_rn(x);
    float r = x - __bfloat162float(hb);
    __nv_bfloat16 lb = __float2bfloat16_rn(r);
    h = __bfloat16_as_ushort(hb);
    l = __bfloat16_as_ushort(lb);
}

// ---------------- prep: fold BN into affine, normalize pos enc ----------------
__global__ void prep_small(const float* __restrict__ W1, const float* __restrict__ g1,
                           const float* __restrict__ b1, const float* __restrict__ m1,
                           const float* __restrict__ v1,
                           const float* __restrict__ W2, const float* __restrict__ g2,
                           const float* __restrict__ b2, const float* __restrict__ m2,
                           const float* __restrict__ v2,
                           const float* __restrict__ pe) {
    int t = threadIdx.x;  // 256 threads
    if (t < 3) {
        float s = g1[t] * rsqrtf(v1[t] + 1e-5f);
        g_t1[t] = b1[t] - m1[t] * s;
    }
    if (t < 9) {
        int j = t % 3;
        float s = g1[j] * rsqrtf(v1[j] + 1e-5f);
        g_W1f[t] = W1[t] * s;
    }
    if (t < C) {
        float s = g2[t] * rsqrtf(v2[t] + 1e-5f);
        g_t2[t] = b2[t] - m2[t] * s;
        for (int i = 0; i < 3; i++) g_W2f[i * C + t] = W2[i * C + t] * s;
    }
    for (int g = t; g < KK * NH; g += blockDim.x) {
        float vals[DD];
        float ss = 0.f;
        for (int d = 0; d < DD; d++) { vals[d] = pe[g * DD + d]; ss += vals[d] * vals[d]; }
        float sc = 1.f / fmaxf(sqrtf(ss), 1e-12f);
        for (int d = 0; d < DD; d++) g_npe[g * DD + d] = vals[d] * sc;
    }
}

// Fold W3 into Wq/Wv
__global__ void prep_fold(const float* __restrict__ W3, const float* __restrict__ b3,
                          const float* __restrict__ Wq, const float* __restrict__ bq,
                          const float* __restrict__ Wv, const float* __restrict__ bv) {
    __shared__ float srow[C];
    int k = blockIdx.x, c = threadIdx.x;
    srow[c] = (k < C) ? W3[k * C + c] : b3[c];
    __syncthreads();
    float aq = 0.f, av = 0.f;
#pragma unroll 4
    for (int j = 0; j < C; j++) {
        float s = srow[j];
        aq = fmaf(s, Wq[j * C + c], aq);
        av = fmaf(s, Wv[j * C + c], av);
    }
    if (k < C) { g_W3q[k * C + c] = aq; g_W3v[k * C + c] = av; }
    else       { g_bq2[c] = bq[c] + aq; g_bv2[c] = bv[c] + av; }
}

// Build bf16 hi/lo weight images B^T[n][k]: n=0..255 (q||v), k=0..255
__global__ void prep_bimg(const float* __restrict__ Wq, const float* __restrict__ Wv) {
    int idx = blockIdx.x * blockDim.x + threadIdx.x;   // 65536 total
    if (idx >= 256 * 256) return;
    int n = idx & 255;
    int k = idx >> 8;
    int nn = n & 127;
    float w;
    if (n < 128) w = (k < 128) ? Wq[k * C + nn] : g_W3q[(k - 128) * C + nn];
    else         w = (k < 128) ? Wv[k * C + nn] : g_W3v[(k - 128) * C + nn];
    unsigned short h, l;
    split1(w, h, l);
    int ch = k >> 6, kk = k & 63;
    g_Bhi[(ch * 256 + n) * KC + kk] = h;
    g_Blo[(ch * 256 + n) * KC + kk] = l;
}

// ---------------- mma.sync Q/V GEMM (bf16-split, fp32-accurate) ----------------
__global__ __launch_bounds__(256, 2) void qv_mma(const float* __restrict__ feats,
                                                 const float* __restrict__ npts) {
    extern __shared__ __align__(16) char smem[];
    const uint32_t sb = smem_u32(smem);
    const int tid  = threadIdx.x;
    const int wid  = tid >> 5;
    const int lane = tid & 31;
    const int wm   = wid & 1;        // 2 m-warps (32 rows each)
    const int wn   = wid >> 1;       // 4 n-warps (64 cols each)
    const int p0   = blockIdx.x * MT;

    float* sbias = (float*)(smem + SBIAS);
    float* sW2   = (float*)(smem + SW2O);
    float* st2   = (float*)(smem + ST2O);
    float* sh1   = (float*)(smem + SH1O);

    // prologue: biases, MLP weights, h1
    sbias[tid] = (tid < 128) ? g_bq2[tid] : g_bv2[tid - 128];
    if (tid < 128) {
        st2[tid] = g_t2[tid];
#pragma unroll
        for (int i = 0; i < 3; i++) sW2[i * 128 + tid] = g_W2f[i * C + tid];
    }
    if (tid < MT) {
        float pp0 = npts[(size_t)(p0 + tid) * 3 + 0];
        float pp1 = npts[(size_t)(p0 + tid) * 3 + 1];
        float pp2 = npts[(size_t)(p0 + tid) * 3 + 2];
#pragma unroll
        for (int j = 0; j < 3; j++) {
            float h = pp0 * g_W1f[j] + pp1 * g_W1f[3 + j] + pp2 * g_W1f[6 + j] + g_t1[j];
            sh1[tid * 3 + j] = fmaxf(h, 0.f);
        }
    }
    __syncthreads();

    float acc[2][8][4];
#pragma unroll
    for (int mi = 0; mi < 2; mi++)
#pragma unroll
        for (int ni = 0; ni < 8; ni++)
#pragma unroll
            for (int e = 0; e < 4; e++) acc[mi][ni][e] = 0.f;

    const int ar = tid >> 2;            // A staging row (64 rows x 4 thr)
    const int acg = (tid & 3) * 16;     // A staging col group

    for (int ch = 0; ch < NCH; ch++) {
        // --- stage A (hi/lo) ---
        {
            float x[16];
            if (ch < 2) {
                const float4* src = (const float4*)(feats + (size_t)(p0 + ar) * C + ch * KC + acg);
#pragma unroll
                for (int b = 0; b < 4; b++) {
                    float4 a = src[b];
                    x[4 * b] = a.x; x[4 * b + 1] = a.y; x[4 * b + 2] = a.z; x[4 * b + 3] = a.w;
                }
            } else {
                float h0 = sh1[ar * 3], h1v = sh1[ar * 3 + 1], h2v = sh1[ar * 3 + 2];
                int c0 = (ch - 2) * KC + acg;
#pragma unroll
                for (int e = 0; e < 16; e++) {
                    int cg = c0 + e;
                    x[e] = fmaxf(h0 * sW2[cg] + h1v * sW2[128 + cg] + h2v * sW2[256 + cg] + st2[cg], 0.f);
                }
            }
            unsigned short hs[16], ls[16];
#pragma unroll
            for (int e = 0; e < 16; e++) split1(x[e], hs[e], ls[e]);
            char* da = smem + SA_HI + (ar * BPAD + acg) * 2;
            char* dl = smem + SA_LO + (ar * BPAD + acg) * 2;
            *(uint4*)(da)      = *(uint4*)(hs);
            *(uint4*)(da + 16) = *(uint4*)(hs + 8);
            *(uint4*)(dl)      = *(uint4*)(ls);
            *(uint4*)(dl + 16) = *(uint4*)(ls + 8);
        }
        // --- stage B (straight copy, repad 64->72) ---
        {
            const uint4* shi = (const uint4*)(g_Bhi + ch * 256 * KC);
            const uint4* slo = (const uint4*)(g_Blo + ch * 256 * KC);
#pragma unroll
            for (int i = 0; i < 8; i++) {
                int f = tid + 256 * i;       // 2048 uint4 per buffer
                int n = f >> 3, kv = f & 7;
                *(uint4*)(smem + SB_HI + n * BPAD * 2 + kv * 16) = shi[f];
                *(uint4*)(smem + SB_LO + n * BPAD * 2 + kv * 16) = slo[f];
            }
        }
        __syncthreads();

        // --- mma over this chunk ---
        const int alr = (lane & 7) + 8 * ((lane >> 3) & 1);
        const int alc = 8 * (lane >> 4);
        const int bnr = (lane & 7) + 8 * (lane >> 4);
        const int bkc = 8 * ((lane >> 3) & 1);
#pragma unroll
        for (int ks = 0; ks < 4; ks++) {
            uint32_t ah[2][4], al[2][4], bb[4][4];
#pragma unroll
            for (int mi = 0; mi < 2; mi++) {
                uint32_t off = ((wm * 32 + mi * 16 + alr) * BPAD + ks * 16 + alc) * 2;
                ldmx4(ah[mi][0], ah[mi][1], ah[mi][2], ah[mi][3], sb + SA_HI + off);
                ldmx4(al[mi][0], al[mi][1], al[mi][2], al[mi][3], sb + SA_LO + off);
            }
            // B hi
#pragma unroll
            for (int p = 0; p < 4; p++) {
                uint32_t off = ((wn * 64 + p * 16 + bnr) * BPAD + ks * 16 + bkc) * 2;
                ldmx4(bb[p][0], bb[p][1], bb[p][2], bb[p][3], sb + SB_HI + off);
            }
#pragma unroll
            for (int mi = 0; mi < 2; mi++)
#pragma unroll
                for (int p = 0; p < 4; p++) {
                    mma16816(acc[mi][2 * p],     ah[mi][0], ah[mi][1], ah[mi][2], ah[mi][3], bb[p][0], bb[p][1]);
                    mma16816(acc[mi][2 * p + 1], ah[mi][0], ah[mi][1], ah[mi][2], ah[mi][3], bb[p][2], bb[p][3]);
                    mma16816(acc[mi][2 * p],     al[mi][0], al[mi][1], al[mi][2], al[mi][3], bb[p][0], bb[p][1]);
                    mma16816(acc[mi][2 * p + 1], al[mi][0], al[mi][1], al[mi][2], al[mi][3], bb[p][2], bb[p][3]);
                }
            // B lo (reuse bb)
#pragma unroll
            for (int p = 0; p < 4; p++) {
                uint32_t off = ((wn * 64 + p * 16 + bnr) * BPAD + ks * 16 + bkc) * 2;
                ldmx4(bb[p][0], bb[p][1], bb[p][2], bb[p][3], sb + SB_LO + off);
            }
#pragma unroll
            for (int mi = 0; mi < 2; mi++)
#pragma unroll
                for (int p = 0; p < 4; p++) {
                    mma16816(acc[mi][2 * p],     ah[mi][0], ah[mi][1], ah[mi][2], ah[mi][3], bb[p][0], bb[p][1]);
                    mma16816(acc[mi][2 * p + 1], ah[mi][0], ah[mi][1], ah[mi][2], ah[mi][3], bb[p][2], bb[p][3]);
                }
        }
        __syncthreads();
    }

    // --- epilogue: bias, per-head L2 norm for q, direct stores ---
    const bool isq = (wn < 2);
    float* dst = isq ? g_nq : g_v;
    const int colbias = wn * 64;                 // 0..255
    const int colout  = (wn & 1) * 64;           // 0..127
#pragma unroll
    for (int mi = 0; mi < 2; mi++) {
#pragma unroll
        for (int ni = 0; ni < 8; ni++) {
            int cb = colbias + ni * 8 + (lane & 3) * 2;
            float b0 = sbias[cb], b1 = sbias[cb + 1];
            acc[mi][ni][0] += b0; acc[mi][ni][1] += b1;
            acc[mi][ni][2] += b0; acc[mi][ni][3] += b1;
        }
        if (isq) {
#pragma unroll
            for (int h = 0; h < 4; h++) {
                float* cA = acc[mi][2 * h];
                float* cB = acc[mi][2 * h + 1];
                float s0 = cA[0] * cA[0] + cA[1] * cA[1] + cB[0] * cB[0] + cB[1] * cB[1];
                float s1 = cA[2] * cA[2] + cA[3] * cA[3] + cB[2] * cB[2] + cB[3] * cB[3];
                s0 += __shfl_xor_sync(0xffffffffu, s0, 1);
                s0 += __shfl_xor_sync(0xffffffffu, s0, 2);
                s1 += __shfl_xor_sync(0xffffffffu, s1, 1);
                s1 += __shfl_xor_sync(0xffffffffu, s1, 2);
                float sc0 = 1.f / fmaxf(sqrtf(s0), 1e-12f);
                float sc1 = 1.f / fmaxf(sqrtf(s1), 1e-12f);
                cA[0] *= sc0; cA[1] *= sc0; cB[0] *= sc0; cB[1] *= sc0;
                cA[2] *= sc1; cA[3] *= sc1; cB[2] *= sc1; cB[3] *= sc1;
            }
        }
        int r0 = p0 + wm * 32 + mi * 16 + (lane >> 2);
#pragma unroll
        for (int ni = 0; ni < 8; ni++) {
            int col = colout + ni * 8 + (lane & 3) * 2;
            *(float2*)(dst + (size_t)r0 * C + col)       = make_float2(acc[mi][ni][0], acc[mi][ni][1]);
            *(float2*)(dst + (size_t)(r0 + 8) * C + col) = make_float2(acc[mi][ni][2], acc[mi][ni][3]);
        }
    }
}

// ---------------- counting sort by query ----------------
__global__ void k_zero_cnt() {
    int i = blockIdx.x * blockDim.x + threadIdx.x;
    if (i < NPTS) g_cnt[i] = 0;
}

__global__ void k_hist(const int* __restrict__ qidx, int M) {
    int i = blockIdx.x * blockDim.x + threadIdx.x;
    int stride = gridDim.x * blockDim.x;
    for (int m = i; m < M; m += stride) atomicAdd(&g_cnt[__ldg(qidx + m)], 1);
}

__global__ __launch_bounds__(1024) void k_scan1() {
    __shared__ int s[1024];
    int i = blockIdx.x * 1024 + threadIdx.x;
    int val = g_cnt[i];
    s[threadIdx.x] = val;
    __syncthreads();
    int acc = val;
#pragma unroll
    for (int off = 1; off < 1024; off <<= 1) {
        int t = (threadIdx.x >= off) ? s[threadIdx.x - off] : 0;
        __syncthreads();
        acc += t;
        s[threadIdx.x] = acc;
        __syncthreads();
    }
    g_part[i] = acc - val;
    if (threadIdx.x == 1023) g_bsum[blockIdx.x] = acc;
}

__global__ void k_scan2() {
    if (threadIdx.x == 0) {
        int run = 0;
        for (int b = 0; b < NPTS / 1024; b++) { g_boff[b] = run; run += g_bsum[b]; }
    }
}

__global__ void k_scan3() {
    int i = blockIdx.x * blockDim.x + threadIdx.x;
    if (i < NPTS) {
        int st = g_part[i] + g_boff[i >> 10];
        g_start[i] = st;
        g_cur[i]   = st;
    }
}

__global__ void k_place(const int* __restrict__ qidx, const int* __restrict__ kidx,
                        const int* __restrict__ kern, int M) {
    int i = blockIdx.x * blockDim.x + threadIdx.x;
    int stride = gridDim.x * blockDim.x;
    for (int m = i; m < M; m += stride) {
        int q = __ldg(qidx + m);
        int pos = atomicAdd(&g_cur[q], 1);
        g_sp[pos] = make_int2(__ldg(kidx + m), __ldg(kern + m));
    }
}

// ---------------- per-query gather + on-the-fly attention ----------------
__global__ __launch_bounds__(256) void gather_acc() {
    __shared__ __align__(16) float s_npe[KK * C];
    for (int i = threadIdx.x; i < KK * C; i += 256) s_npe[i] = g_npe[i];
    __syncthreads();

    const int lane    = threadIdx.x & 31;
    const int warp    = (blockIdx.x * 256 + threadIdx.x) >> 5;
    const int nwarps  = (gridDim.x * 256) >> 5;
    const float4* v4  = reinterpret_cast<const float4*>(g_v);
    const float4* nq4 = reinterpret_cast<const float4*>(g_nq);
    const float4* pe4 = reinterpret_cast<const float4*>(s_npe);

    for (int q = warp; q < NPTS; q += nwarps) {
        int s = g_start[q];
        int n = g_cnt[q];
        float4 aqv = nq4[(size_t)q * 32 + lane];
        float4 acc = make_float4(0.f, 0.f, 0.f, 0.f);

        for (int base = 0; base < n; base += 32) {
            int take = n - base; if (take > 32) take = 32;
            int2 pl = (lane < take) ? g_sp[s + base + lane] : make_int2(0, 0);
            int j = 0;
#pragma unroll 4
            for (; j < take; j++) {
                int key = __shfl_sync(0xffffffffu, pl.x, j);
                int kk  = __shfl_sync(0xffffffffu, pl.y, j);
                float4 b = pe4[kk * 32 + lane];
                float part = aqv.x * b.x + aqv.y * b.y + aqv.z * b.z + aqv.w * b.w;
                part += __shfl_xor_sync(0xffffffffu, part, 1);
                part += __shfl_xor_sync(0xffffffffu, part, 2);
                float4 vv = v4[(size_t)key * 32 + lane];
                acc.x = fmaf(part, vv.x, acc.x);
                acc.y = fmaf(part, vv.y, acc.y);
                acc.z = fmaf(part, vv.z, acc.z);
                acc.w = fmaf(part, vv.w, acc.w);
            }
        }
        reinterpret_cast<float4*>(g_acc)[(size_t)q * 32 + lane] = acc;
    }
}

// ---------------- epilogue GEMM: out = acc @ Wo + bo ----------------
__global__ __launch_bounds__(128) void out_kernel(const float* __restrict__ Wo,
                                                  const float* __restrict__ bo,
                                                  float* __restrict__ out) {
    __shared__ __align__(16) float sa[C][SPAD];
    const int c = threadIdx.x;
    const int n0 = blockIdx.x * TP;

#pragma unroll
    for (int p = 0; p < TP; p++) sa[c][p] = g_acc[(size_t)(n0 + p) * C + c];
    __syncthreads();

    float b = bo[c];
    float2 acc[TP / 2];
#pragma unroll
    for (int i = 0; i < TP / 2; i++) acc[i] = make_float2(b, b);

#pragma unroll 2
    for (int k = 0; k < C; k++) {
        float2 w = bc2(Wo[k * C + c]);
        const float4* a4 = reinterpret_cast<const float4*>(&sa[k][0]);
#pragma unroll
        for (int i = 0; i < TP / 4; i++) {
            float4 f = a4[i];
            acc[2 * i]     = ffma2(make_float2(f.x, f.y), w, acc[2 * i]);
            acc[2 * i + 1] = ffma2(make_float2(f.z, f.w), w, acc[2 * i + 1]);
        }
    }
#pragma unroll
    for (int i = 0; i < TP / 2; i++) {
        size_t n = (size_t)(n0 + 2 * i);
        out[n * C + c]       = acc[i].x;
        out[(n + 1) * C + c] = acc[i].y;
    }
}

// ---------------- launch ----------------
extern "C" void kernel_launch(void* const* d_in, const int* in_sizes, int n_in,
                              void* d_out, int out_size) {
    const float* feats = (const float*)d_in[0];
    const float* npts  = (const float*)d_in[1];
    const float* Wq    = (const float*)d_in[2];
    const float* bq    = (const float*)d_in[3];
    const float* Wv    = (const float*)d_in[4];
    const float* bv    = (const float*)d_in[5];
    const float* Wo    = (const float*)d_in[6];
    const float* bo    = (const float*)d_in[7];
    const float* pe    = (const float*)d_in[8];
    const float* W1    = (const float*)d_in[9];
    const float* g1    = (const float*)d_in[10];
    const float* b1    = (const float*)d_in[11];
    const float* m1    = (const float*)d_in[12];
    const float* v1    = (const float*)d_in[13];
    const float* W2    = (const float*)d_in[14];
    const float* g2    = (const float*)d_in[15];
    const float* b2    = (const float*)d_in[16];
    const float* m2    = (const float*)d_in[17];
    const float* v2    = (const float*)d_in[18];
    const float* W3    = (const float*)d_in[19];
    const float* b3    = (const float*)d_in[20];
    const int* qi      = (const int*)d_in[21];
    const int* ki      = (const int*)d_in[22];
    const int* kk      = (const int*)d_in[23];

    const int M = in_sizes[21];
    const int n = in_sizes[0] / C;   // 131072

    cudaFuncSetAttribute(qv_mma, cudaFuncAttributeMaxDynamicSharedMemorySize, QV_SMEM);

    prep_small<<<1, 256>>>(W1, g1, b1, m1, v1, W2, g2, b2, m2, v2, pe);
    prep_fold<<<C + 1, 128>>>(W3, b3, Wq, bq, Wv, bv);
    prep_bimg<<<256, 256>>>(Wq, Wv);
    qv_mma<<<n / MT, 256, QV_SMEM>>>(feats, npts);

    // counting sort by query
    k_zero_cnt<<<(NPTS + 255) / 256, 256>>>();
    k_hist<<<1024, 256>>>(qi, M);
    k_scan1<<<NPTS / 1024, 1024>>>();
    k_scan2<<<1, 32>>>();
    k_scan3<<<(NPTS + 255) / 256, 256>>>();
    k_place<<<1024, 256>>>(qi, ki, kk, M);

    gather_acc<<<2048, 256>>>();
    out_kernel<<<n / TP, 128>>>(Wo, bo, (float*)d_out);
}